// round 1
// baseline (speedup 1.0000x reference)
#include <cuda_runtime.h>
#include <math.h>

// Problem constants
// B=32, H=W=64, C=192, WS=8, SS=4, NH=6, HD=32, N=64 tokens/window, NW=64 windows/img
// Window-order rows: r in [0, 131072), r = (b*64 + w)*64 + n

#define NROWS 131072
#define CDIM  192
#define QKV_STRIDE 25165824ll  // 131072*192

// Scratch (device globals; no allocation allowed)
__device__ float g_qkv[3ll * 25165824];   // [which][ (wid*6+head)*64 + n ][32]
__device__ float g_att[25165824];         // (B_, N, C) window order
__device__ float g_x1[25165824];          // residual-1 output, token order
__device__ float g_h[100663296ll];        // (tokens, 768)

// window-order row -> original token index (roll by -4 fused with window partition)
__device__ __forceinline__ int map_row(int r) {
    int wid = r >> 6, n = r & 63;
    int b = wid >> 6, w = wid & 63;
    int h  = ((w >> 3) << 3) + (n >> 3);
    int ww = ((w & 7) << 3) + (n & 7);
    int ho = (h + 4) & 63, wo = (ww + 4) & 63;
    return (b << 12) + (ho << 6) + wo;
}

__device__ __forceinline__ int region(int x) { return x < 56 ? 0 : (x < 60 ? 1 : 2); }

// ---------------------------------------------------------------------------
// Tiled fp32 GEMM: 64x64 block tile, BK=16, 256 threads, 4x4 per thread.
// MODE 0: QKV  (A rows gathered via map_row; cols scattered to g_qkv, q scaled)
// MODE 1: proj (rows scattered via map_row; out = aux[orig] + acc + bias)
// MODE 2: fc1  (out = gelu(acc+bias))
// MODE 3: fc2  (out = aux + acc + bias)
// ---------------------------------------------------------------------------
template<int MODE, int K, int NCOLS>
__global__ __launch_bounds__(256) void gemm_kernel(
    const float* __restrict__ A, const float* __restrict__ Bm,
    const float* __restrict__ bias, const float* __restrict__ aux,
    float* __restrict__ out)
{
    __shared__ float As[64][16];
    __shared__ float Bs[16][64];

    const int mBase = blockIdx.y * 64;
    const int nBase = blockIdx.x * 64;
    const int t  = threadIdx.x;
    const int tx = t & 15, ty = t >> 4;

    // loader mapping
    const int am = t >> 2;          // 0..63 row of A tile
    const int ak = (t & 3) << 2;    // 0,4,8,12
    const int bk = t >> 4;          // 0..15 row of B tile
    const int bn = (t & 15) << 2;   // col*4

    long arow;
    if (MODE == 0) arow = (long)map_row(mBase + am) * K;
    else           arow = (long)(mBase + am) * K;
    const float* Aptr = A + arow + ak;
    const float* Bptr = Bm + (long)bk * NCOLS + nBase + bn;

    float acc[4][4] = {};

    for (int kt = 0; kt < K; kt += 16) {
        float4 av = *(const float4*)(Aptr + kt);
        float4 bv = *(const float4*)(Bptr + (long)kt * NCOLS);
        *(float4*)&As[am][ak] = av;
        *(float4*)&Bs[bk][bn] = bv;
        __syncthreads();
        #pragma unroll
        for (int k = 0; k < 16; k++) {
            float a0 = As[ty * 4 + 0][k];
            float a1 = As[ty * 4 + 1][k];
            float a2 = As[ty * 4 + 2][k];
            float a3 = As[ty * 4 + 3][k];
            float4 b4 = *(const float4*)&Bs[k][tx * 4];
            acc[0][0] += a0 * b4.x; acc[0][1] += a0 * b4.y; acc[0][2] += a0 * b4.z; acc[0][3] += a0 * b4.w;
            acc[1][0] += a1 * b4.x; acc[1][1] += a1 * b4.y; acc[1][2] += a1 * b4.z; acc[1][3] += a1 * b4.w;
            acc[2][0] += a2 * b4.x; acc[2][1] += a2 * b4.y; acc[2][2] += a2 * b4.z; acc[2][3] += a2 * b4.w;
            acc[3][0] += a3 * b4.x; acc[3][1] += a3 * b4.y; acc[3][2] += a3 * b4.z; acc[3][3] += a3 * b4.w;
        }
        __syncthreads();
    }

    #pragma unroll
    for (int i = 0; i < 4; i++) {
        int r = mBase + ty * 4 + i;
        #pragma unroll
        for (int j = 0; j < 4; j++) {
            int c = nBase + tx * 4 + j;
            float v = acc[i][j] + bias[c];
            if (MODE == 0) {
                int which = c / 192, rem = c % 192;
                int head = rem >> 5, hd = rem & 31;
                if (which == 0) v *= 0.17677669529663689f;  // HD^-0.5
                int wid = r >> 6, n = r & 63;
                out[(long)which * QKV_STRIDE +
                    (((long)(wid * 6 + head) * 64 + n) * 32 + hd)] = v;
            } else if (MODE == 1) {
                long o = (long)map_row(r) * 192 + c;
                out[o] = aux[o] + v;
            } else if (MODE == 2) {
                out[(long)r * NCOLS + c] = 0.5f * v * (1.0f + erff(v * 0.7071067811865476f));
            } else {
                long o = (long)r * NCOLS + c;
                out[o] = aux[o] + v;
            }
        }
    }
}

// ---------------------------------------------------------------------------
// Attention: one block per (window, head). N=64, HD=32.
// Scores + rel-pos bias + shift mask + softmax + PV, all in smem/regs.
// ---------------------------------------------------------------------------
__global__ __launch_bounds__(128) void attn_kernel(
    const float* __restrict__ rpb, float* __restrict__ out)
{
    __shared__ float Qs[64][32];
    __shared__ float Ks[64][32];
    __shared__ float Vs[64][32];
    __shared__ float S[64][65];

    const int bh = blockIdx.x;            // wid*6 + head
    const int wid = bh / 6, head = bh - wid * 6;
    const int w = wid & 63;               // window index within image
    const int t = threadIdx.x;

    const float* qb = g_qkv + (long)bh * 2048;
    const float* kb = qb + QKV_STRIDE;
    const float* vb = kb + QKV_STRIDE;

    #pragma unroll
    for (int i = t; i < 512; i += 128) {
        ((float4*)Qs)[i] = ((const float4*)qb)[i];
        ((float4*)Ks)[i] = ((const float4*)kb)[i];
        ((float4*)Vs)[i] = ((const float4*)vb)[i];
    }
    __syncthreads();

    const int row = t >> 1, half = t & 1;
    const int cb = half << 5;

    float q[32];
    #pragma unroll
    for (int i = 0; i < 8; i++) {
        float4 v = *(const float4*)&Qs[row][i * 4];
        q[i * 4] = v.x; q[i * 4 + 1] = v.y; q[i * 4 + 2] = v.z; q[i * 4 + 3] = v.w;
    }

    const int hb  = (w >> 3) << 3;   // window base h (rolled coords)
    const int wbx = (w & 7) << 3;    // window base w
    const int rh = row >> 3, rw = row & 7;
    const int regRow = region(hb + rh) * 3 + region(wbx + rw);

    float mx = -1e30f;
    for (int c = 0; c < 32; c++) {
        int col = cb + c;
        float acc = 0.f;
        const float* kp = &Ks[col][0];
        #pragma unroll
        for (int i = 0; i < 8; i++) {
            float4 kv = *(const float4*)(kp + i * 4);
            acc += q[i * 4] * kv.x + q[i * 4 + 1] * kv.y +
                   q[i * 4 + 2] * kv.z + q[i * 4 + 3] * kv.w;
        }
        int ch = col >> 3, cw = col & 7;
        acc += rpb[((rh - ch + 7) * 15 + (rw - cw + 7)) * 6 + head];
        int regC = region(hb + ch) * 3 + region(wbx + cw);
        if (regC != regRow) acc -= 100.f;
        S[row][col] = acc;
        mx = fmaxf(mx, acc);
    }
    mx = fmaxf(mx, __shfl_xor_sync(0xffffffffu, mx, 1));

    float lsum = 0.f;
    for (int c = 0; c < 32; c++) {
        float e = __expf(S[row][cb + c] - mx);
        S[row][cb + c] = e;
        lsum += e;
    }
    lsum += __shfl_xor_sync(0xffffffffu, lsum, 1);
    float inv = 1.f / lsum;
    __syncthreads();

    // PV: each thread computes 16 output dims of its row
    float o[16] = {};
    const int hd0 = half << 4;
    for (int m = 0; m < 64; m++) {
        float p = S[row][m];
        const float* vp = &Vs[m][hd0];
        #pragma unroll
        for (int i = 0; i < 4; i++) {
            float4 vv = *(const float4*)(vp + i * 4);
            o[i * 4]     += p * vv.x;
            o[i * 4 + 1] += p * vv.y;
            o[i * 4 + 2] += p * vv.z;
            o[i * 4 + 3] += p * vv.w;
        }
    }
    float* op = out + ((long)(wid * 64 + row)) * 192 + head * 32 + hd0;
    #pragma unroll
    for (int i = 0; i < 16; i++) op[i] = o[i] * inv;
}

// ---------------------------------------------------------------------------
extern "C" void kernel_launch(void* const* d_in, const int* in_sizes, int n_in,
                              void* d_out, int out_size)
{
    const float* x      = (const float*)d_in[0];
    const float* rpb    = (const float*)d_in[1];
    const float* qkv_w  = (const float*)d_in[2];
    const float* qkv_b  = (const float*)d_in[3];
    const float* proj_w = (const float*)d_in[4];
    const float* proj_b = (const float*)d_in[5];
    const float* fc1_w  = (const float*)d_in[6];
    const float* fc1_b  = (const float*)d_in[7];
    const float* fc2_w  = (const float*)d_in[8];
    const float* fc2_b  = (const float*)d_in[9];
    float* out = (float*)d_out;

    float *qkv, *att, *x1, *h;
    cudaGetSymbolAddress((void**)&qkv, g_qkv);
    cudaGetSymbolAddress((void**)&att, g_att);
    cudaGetSymbolAddress((void**)&x1,  g_x1);
    cudaGetSymbolAddress((void**)&h,   g_h);

    dim3 blk(256);
    // 1) QKV projection (gathered rows = roll + window partition), q pre-scaled
    gemm_kernel<0, 192, 576><<<dim3(576 / 64, NROWS / 64), blk>>>(x, qkv_w, qkv_b, nullptr, qkv);
    // 2) windowed attention
    attn_kernel<<<12288, 128>>>(rpb, att);
    // 3) proj + window reverse + roll back + residual
    gemm_kernel<1, 192, 192><<<dim3(192 / 64, NROWS / 64), blk>>>(att, proj_w, proj_b, x, x1);
    // 4) fc1 + exact GELU
    gemm_kernel<2, 192, 768><<<dim3(768 / 64, NROWS / 64), blk>>>(x1, fc1_w, fc1_b, nullptr, h);
    // 5) fc2 + residual -> out
    gemm_kernel<3, 768, 192><<<dim3(192 / 64, NROWS / 64), blk>>>(h, fc2_w, fc2_b, x1, out);
}

// round 2
// speedup vs baseline: 1.7689x; 1.7689x over previous
#include <cuda_runtime.h>
#include <math.h>

#define NROWS 131072
#define QKV_STRIDE 25165824ll  // 131072*192

__device__ float g_qkv[3ll * 25165824];
__device__ float g_att[25165824];
__device__ float g_x1[25165824];
__device__ float g_h[100663296ll];

__device__ __forceinline__ int map_row(int r) {
    int wid = r >> 6, n = r & 63;
    int b = wid >> 6, w = wid & 63;
    int h  = ((w >> 3) << 3) + (n >> 3);
    int ww = ((w & 7) << 3) + (n & 7);
    int ho = (h + 4) & 63, wo = (ww + 4) & 63;
    return (b << 12) + (ho << 6) + wo;
}

__device__ __forceinline__ int region(int x) { return x < 56 ? 0 : (x < 60 ? 1 : 2); }

__device__ __forceinline__ unsigned f2tf32(float f) {
    unsigned u; asm("cvt.rna.tf32.f32 %0, %1;" : "=r"(u) : "f"(f)); return u;
}

__device__ __forceinline__ void mma_tf32(float* d, const unsigned* a, const unsigned* b) {
    asm volatile(
        "mma.sync.aligned.m16n8k8.row.col.f32.tf32.tf32.f32 "
        "{%0,%1,%2,%3}, {%4,%5,%6,%7}, {%8,%9}, {%0,%1,%2,%3};"
        : "+f"(d[0]), "+f"(d[1]), "+f"(d[2]), "+f"(d[3])
        : "r"(a[0]), "r"(a[1]), "r"(a[2]), "r"(a[3]), "r"(b[0]), "r"(b[1]));
}

template<int MODE, int NCOLS>
__device__ __forceinline__ void epi_store(
    int r, int c, float v, const float* __restrict__ bias,
    const float* __restrict__ aux, float* __restrict__ out)
{
    v += bias[c];
    if (MODE == 0) {
        int which = c / 192, rem = c % 192;
        int head = rem >> 5, hd = rem & 31;
        if (which == 0) v *= 0.17677669529663689f;
        int wid = r >> 6, n = r & 63;
        out[(long)which * QKV_STRIDE + (((long)(wid * 6 + head) * 64 + n) * 32 + hd)] = v;
    } else if (MODE == 1) {
        long o = (long)map_row(r) * 192 + c;
        out[o] = aux[o] + v;
    } else if (MODE == 2) {
        out[(long)r * NCOLS + c] = 0.5f * v * (1.0f + erff(v * 0.7071067811865476f));
    } else {
        long o = (long)r * NCOLS + c;
        out[o] = aux[o] + v;
    }
}

// ---------------------------------------------------------------------------
// tf32 tensor-core GEMM: 128x64 block tile, BK=16, 256 thr = 8 warps (4x2),
// warp tile 32x32 = 2x4 m16n8k8 fragments. A smem transposed [k][m] pad 8,
// B smem [k][n] pad 8 -> conflict-free fragment LDS.
// ---------------------------------------------------------------------------
template<int MODE, int K, int NCOLS>
__global__ __launch_bounds__(256) void gemm_mma(
    const float* __restrict__ A, const float* __restrict__ Bm,
    const float* __restrict__ bias, const float* __restrict__ aux,
    float* __restrict__ out)
{
    __shared__ unsigned As[16][136];   // [k][m]
    __shared__ unsigned Bs[16][72];    // [k][n]

    const int mBase = blockIdx.y * 128;
    const int nBase = blockIdx.x * 64;
    const int t = threadIdx.x;
    const int lane = t & 31, warp = t >> 5;
    const int warpM = warp >> 1, warpN = warp & 1;
    const int lq = lane >> 2, lr = lane & 3;   // quad row / col

    // A loader: rows am1, am1+64; k = ak..ak+3
    const int am1 = t >> 2;
    const int ak  = (t & 3) << 2;
    long arow1, arow2;
    if (MODE == 0) {
        arow1 = (long)map_row(mBase + am1) * K;
        arow2 = (long)map_row(mBase + am1 + 64) * K;
    } else {
        arow1 = (long)(mBase + am1) * K;
        arow2 = (long)(mBase + am1 + 64) * K;
    }
    const float* Ap1 = A + arow1 + ak;
    const float* Ap2 = A + arow2 + ak;

    // B loader: k = t>>4, n = (t&15)*4
    const int bk = t >> 4;
    const int bn = (t & 15) << 2;
    const float* Bp = Bm + (long)bk * NCOLS + nBase + bn;

    float acc[2][4][4];
    #pragma unroll
    for (int i = 0; i < 2; i++)
        #pragma unroll
        for (int j = 0; j < 4; j++)
            #pragma unroll
            for (int e = 0; e < 4; e++) acc[i][j][e] = 0.f;

    float4 aR1 = *(const float4*)Ap1;
    float4 aR2 = *(const float4*)Ap2;
    float4 bR  = *(const float4*)Bp;

    for (int kt = 0; kt < K; kt += 16) {
        // store current tile (convert to tf32)
        As[ak + 0][am1] = f2tf32(aR1.x); As[ak + 1][am1] = f2tf32(aR1.y);
        As[ak + 2][am1] = f2tf32(aR1.z); As[ak + 3][am1] = f2tf32(aR1.w);
        As[ak + 0][am1 + 64] = f2tf32(aR2.x); As[ak + 1][am1 + 64] = f2tf32(aR2.y);
        As[ak + 2][am1 + 64] = f2tf32(aR2.z); As[ak + 3][am1 + 64] = f2tf32(aR2.w);
        Bs[bk][bn + 0] = f2tf32(bR.x); Bs[bk][bn + 1] = f2tf32(bR.y);
        Bs[bk][bn + 2] = f2tf32(bR.z); Bs[bk][bn + 3] = f2tf32(bR.w);
        __syncthreads();

        if (kt + 16 < K) {  // prefetch next tile
            aR1 = *(const float4*)(Ap1 + kt + 16);
            aR2 = *(const float4*)(Ap2 + kt + 16);
            bR  = *(const float4*)(Bp + (long)(kt + 16) * NCOLS);
        }

        #pragma unroll
        for (int k0 = 0; k0 < 16; k0 += 8) {
            unsigned a[2][4], b[4][2];
            #pragma unroll
            for (int mi = 0; mi < 2; mi++) {
                int m0 = warpM * 32 + mi * 16 + lq;
                a[mi][0] = As[k0 + lr][m0];
                a[mi][1] = As[k0 + lr][m0 + 8];
                a[mi][2] = As[k0 + lr + 4][m0];
                a[mi][3] = As[k0 + lr + 4][m0 + 8];
            }
            #pragma unroll
            for (int ni = 0; ni < 4; ni++) {
                int n0 = warpN * 32 + ni * 8 + lq;
                b[ni][0] = Bs[k0 + lr][n0];
                b[ni][1] = Bs[k0 + lr + 4][n0];
            }
            #pragma unroll
            for (int mi = 0; mi < 2; mi++)
                #pragma unroll
                for (int ni = 0; ni < 4; ni++)
                    mma_tf32(acc[mi][ni], a[mi], b[ni]);
        }
        __syncthreads();
    }

    // epilogue: c0/c1 at (row, col), c2/c3 at (row+8, col)
    #pragma unroll
    for (int mi = 0; mi < 2; mi++) {
        int r0 = mBase + warpM * 32 + mi * 16 + lq;
        #pragma unroll
        for (int ni = 0; ni < 4; ni++) {
            int c0 = nBase + warpN * 32 + ni * 8 + lr * 2;
            epi_store<MODE, NCOLS>(r0,     c0,     acc[mi][ni][0], bias, aux, out);
            epi_store<MODE, NCOLS>(r0,     c0 + 1, acc[mi][ni][1], bias, aux, out);
            epi_store<MODE, NCOLS>(r0 + 8, c0,     acc[mi][ni][2], bias, aux, out);
            epi_store<MODE, NCOLS>(r0 + 8, c0 + 1, acc[mi][ni][3], bias, aux, out);
        }
    }
}

// ---------------------------------------------------------------------------
// Attention: one block per (window, head). N=64, HD=32. (unchanged)
// ---------------------------------------------------------------------------
__global__ __launch_bounds__(128) void attn_kernel(
    const float* __restrict__ rpb, float* __restrict__ out)
{
    __shared__ float Qs[64][32];
    __shared__ float Ks[64][32];
    __shared__ float Vs[64][32];
    __shared__ float S[64][65];

    const int bh = blockIdx.x;
    const int wid = bh / 6, head = bh - wid * 6;
    const int w = wid & 63;
    const int t = threadIdx.x;

    const float* qb = g_qkv + (long)bh * 2048;
    const float* kb = qb + QKV_STRIDE;
    const float* vb = kb + QKV_STRIDE;

    #pragma unroll
    for (int i = t; i < 512; i += 128) {
        ((float4*)Qs)[i] = ((const float4*)qb)[i];
        ((float4*)Ks)[i] = ((const float4*)kb)[i];
        ((float4*)Vs)[i] = ((const float4*)vb)[i];
    }
    __syncthreads();

    const int row = t >> 1, half = t & 1;
    const int cb = half << 5;

    float q[32];
    #pragma unroll
    for (int i = 0; i < 8; i++) {
        float4 v = *(const float4*)&Qs[row][i * 4];
        q[i * 4] = v.x; q[i * 4 + 1] = v.y; q[i * 4 + 2] = v.z; q[i * 4 + 3] = v.w;
    }

    const int hb  = (w >> 3) << 3;
    const int wbx = (w & 7) << 3;
    const int rh = row >> 3, rw = row & 7;
    const int regRow = region(hb + rh) * 3 + region(wbx + rw);

    float mx = -1e30f;
    for (int c = 0; c < 32; c++) {
        int col = cb + c;
        float acc = 0.f;
        const float* kp = &Ks[col][0];
        #pragma unroll
        for (int i = 0; i < 8; i++) {
            float4 kv = *(const float4*)(kp + i * 4);
            acc += q[i * 4] * kv.x + q[i * 4 + 1] * kv.y +
                   q[i * 4 + 2] * kv.z + q[i * 4 + 3] * kv.w;
        }
        int ch = col >> 3, cw = col & 7;
        acc += rpb[((rh - ch + 7) * 15 + (rw - cw + 7)) * 6 + head];
        int regC = region(hb + ch) * 3 + region(wbx + cw);
        if (regC != regRow) acc -= 100.f;
        S[row][col] = acc;
        mx = fmaxf(mx, acc);
    }
    mx = fmaxf(mx, __shfl_xor_sync(0xffffffffu, mx, 1));

    float lsum = 0.f;
    for (int c = 0; c < 32; c++) {
        float e = __expf(S[row][cb + c] - mx);
        S[row][cb + c] = e;
        lsum += e;
    }
    lsum += __shfl_xor_sync(0xffffffffu, lsum, 1);
    float inv = 1.f / lsum;
    __syncthreads();

    float o[16] = {};
    const int hd0 = half << 4;
    for (int m = 0; m < 64; m++) {
        float p = S[row][m];
        const float* vp = &Vs[m][hd0];
        #pragma unroll
        for (int i = 0; i < 4; i++) {
            float4 vv = *(const float4*)(vp + i * 4);
            o[i * 4]     += p * vv.x;
            o[i * 4 + 1] += p * vv.y;
            o[i * 4 + 2] += p * vv.z;
            o[i * 4 + 3] += p * vv.w;
        }
    }
    float* op = out + ((long)(wid * 64 + row)) * 192 + head * 32 + hd0;
    #pragma unroll
    for (int i = 0; i < 16; i++) op[i] = o[i] * inv;
}

// ---------------------------------------------------------------------------
extern "C" void kernel_launch(void* const* d_in, const int* in_sizes, int n_in,
                              void* d_out, int out_size)
{
    const float* x      = (const float*)d_in[0];
    const float* rpb    = (const float*)d_in[1];
    const float* qkv_w  = (const float*)d_in[2];
    const float* qkv_b  = (const float*)d_in[3];
    const float* proj_w = (const float*)d_in[4];
    const float* proj_b = (const float*)d_in[5];
    const float* fc1_w  = (const float*)d_in[6];
    const float* fc1_b  = (const float*)d_in[7];
    const float* fc2_w  = (const float*)d_in[8];
    const float* fc2_b  = (const float*)d_in[9];
    float* out = (float*)d_out;

    float *qkv, *att, *x1, *h;
    cudaGetSymbolAddress((void**)&qkv, g_qkv);
    cudaGetSymbolAddress((void**)&att, g_att);
    cudaGetSymbolAddress((void**)&x1,  g_x1);
    cudaGetSymbolAddress((void**)&h,   g_h);

    dim3 blk(256);
    gemm_mma<0, 192, 576><<<dim3(576 / 64, NROWS / 128), blk>>>(x, qkv_w, qkv_b, nullptr, qkv);
    attn_kernel<<<12288, 128>>>(rpb, att);
    gemm_mma<1, 192, 192><<<dim3(192 / 64, NROWS / 128), blk>>>(att, proj_w, proj_b, x, x1);
    gemm_mma<2, 192, 768><<<dim3(768 / 64, NROWS / 128), blk>>>(x1, fc1_w, fc1_b, nullptr, h);
    gemm_mma<3, 768, 192><<<dim3(192 / 64, NROWS / 128), blk>>>(h, fc2_w, fc2_b, x1, out);
}

// round 3
// speedup vs baseline: 2.2847x; 1.2916x over previous
#include <cuda_runtime.h>
#include <cuda_bf16.h>
#include <math.h>

#define NROWS 131072
#define QKV_STRIDE 25165824ll  // 131072*192

__device__ float g_qkv[3ll * 25165824];
__device__ float g_att[25165824];
__device__ float g_x1[25165824];
__device__ float g_h[100663296ll];

__device__ __forceinline__ int map_row(int r) {
    int wid = r >> 6, n = r & 63;
    int b = wid >> 6, w = wid & 63;
    int h  = ((w >> 3) << 3) + (n >> 3);
    int ww = ((w & 7) << 3) + (n & 7);
    int ho = (h + 4) & 63, wo = (ww + 4) & 63;
    return (b << 12) + (ho << 6) + wo;
}

__device__ __forceinline__ int region(int x) { return x < 56 ? 0 : (x < 60 ? 1 : 2); }

__device__ __forceinline__ unsigned pack2(float e, float o) {
    __nv_bfloat162 h = __floats2bfloat162_rn(e, o);   // lo = e (even k), hi = o (odd k)
    return *reinterpret_cast<unsigned*>(&h);
}

__device__ __forceinline__ void mma_bf16(float* d, const unsigned* a, const unsigned* b) {
    asm volatile(
        "mma.sync.aligned.m16n8k16.row.col.f32.bf16.bf16.f32 "
        "{%0,%1,%2,%3}, {%4,%5,%6,%7}, {%8,%9}, {%0,%1,%2,%3};"
        : "+f"(d[0]), "+f"(d[1]), "+f"(d[2]), "+f"(d[3])
        : "r"(a[0]), "r"(a[1]), "r"(a[2]), "r"(a[3]), "r"(b[0]), "r"(b[1]));
}

template<int MODE, int NCOLS>
__device__ __forceinline__ void epi_store(
    int r, int c, float v, const float* __restrict__ bias,
    const float* __restrict__ aux, float* __restrict__ out)
{
    v += bias[c];
    if (MODE == 0) {
        int which = c / 192, rem = c % 192;
        int head = rem >> 5, hd = rem & 31;
        if (which == 0) v *= 0.17677669529663689f;
        int wid = r >> 6, n = r & 63;
        out[(long)which * QKV_STRIDE + (((long)(wid * 6 + head) * 64 + n) * 32 + hd)] = v;
    } else if (MODE == 1) {
        long o = (long)map_row(r) * 192 + c;
        out[o] = aux[o] + v;
    } else if (MODE == 2) {
        out[(long)r * NCOLS + c] = 0.5f * v * (1.0f + erff(v * 0.7071067811865476f));
    } else {
        long o = (long)r * NCOLS + c;
        out[o] = aux[o] + v;
    }
}

// ---------------------------------------------------------------------------
// bf16 tensor-core GEMM: block 256x64, BK=16, 8 warps (4x2), warp tile 64x32
// = 4x4 m16n8k16 frags. Pair-packed smem ([kpair][m]/[kpair][n], even-k lo).
// Double-buffered smem, 1 sync/iter, register prefetch.
// ---------------------------------------------------------------------------
template<int MODE, int K, int NCOLS>
__global__ __launch_bounds__(256, 2) void gemm_bf16(
    const float* __restrict__ A, const float* __restrict__ Bm,
    const float* __restrict__ bias, const float* __restrict__ aux,
    float* __restrict__ out)
{
    __shared__ __align__(16) unsigned As[2][8][268];  // [buf][kpair][m]
    __shared__ __align__(16) unsigned Bs[2][8][72];   // [buf][kpair][n]

    const int mBase = blockIdx.y * 256;
    const int nBase = blockIdx.x * 64;
    const int t = threadIdx.x;
    const int lane = t & 31, warp = t >> 5;
    const int warpM = warp >> 1, warpN = warp & 1;
    const int lq = lane >> 2, lr = lane & 3;

    // A loader: 4 rows (m = t>>2 + 64i), k chunk (t&3)*4
    const int k4 = (t & 3) << 2;
    const int kp = k4 >> 1;           // kpair row (0,2,4,6)
    const int amr = t >> 2;
    const float* Ap[4];
    #pragma unroll
    for (int i = 0; i < 4; i++) {
        int m = amr + 64 * i;
        long row = (MODE == 0) ? (long)map_row(mBase + m) : (long)(mBase + m);
        Ap[i] = A + row * K + k4;
    }
    // B loader (threads < 128): kpair = t>>4, n = (t&15)*4
    const int bp = t >> 4;
    const int bn4 = (t & 15) << 2;
    const float* Bp0 = Bm + (long)(2 * bp) * NCOLS + nBase + bn4;
    const float* Bp1 = Bp0 + NCOLS;

    float acc[4][4][4];
    #pragma unroll
    for (int mi = 0; mi < 4; mi++)
        #pragma unroll
        for (int ni = 0; ni < 4; ni++)
            #pragma unroll
            for (int e = 0; e < 4; e++) acc[mi][ni][e] = 0.f;

    float4 aR[4];
    float4 bR0, bR1;
    #pragma unroll
    for (int i = 0; i < 4; i++) aR[i] = *(const float4*)Ap[i];
    if (t < 128) { bR0 = *(const float4*)Bp0; bR1 = *(const float4*)Bp1; }

    const int NK = K / 16;
    for (int kt = 0; kt < NK; kt++) {
        const int buf = kt & 1;
        // store current tile (pack fp32 pairs -> bf16x2)
        #pragma unroll
        for (int i = 0; i < 4; i++) {
            int m = amr + 64 * i;
            As[buf][kp][m]     = pack2(aR[i].x, aR[i].y);
            As[buf][kp + 1][m] = pack2(aR[i].z, aR[i].w);
        }
        if (t < 128) {
            uint4 pb;
            pb.x = pack2(bR0.x, bR1.x);
            pb.y = pack2(bR0.y, bR1.y);
            pb.z = pack2(bR0.z, bR1.z);
            pb.w = pack2(bR0.w, bR1.w);
            *(uint4*)&Bs[buf][bp][bn4] = pb;
        }
        __syncthreads();

        if (kt + 1 < NK) {  // prefetch next tile into regs
            #pragma unroll
            for (int i = 0; i < 4; i++) aR[i] = *(const float4*)(Ap[i] + (kt + 1) * 16);
            if (t < 128) {
                bR0 = *(const float4*)(Bp0 + (long)(kt + 1) * 16 * NCOLS);
                bR1 = *(const float4*)(Bp1 + (long)(kt + 1) * 16 * NCOLS);
            }
        }

        // fragment loads (conflict-free) + 16 mma
        unsigned af[4][4], bf[4][2];
        #pragma unroll
        for (int mi = 0; mi < 4; mi++) {
            int m0 = warpM * 64 + mi * 16 + lq;
            af[mi][0] = As[buf][lr][m0];
            af[mi][1] = As[buf][lr][m0 + 8];
            af[mi][2] = As[buf][lr + 4][m0];
            af[mi][3] = As[buf][lr + 4][m0 + 8];
        }
        #pragma unroll
        for (int ni = 0; ni < 4; ni++) {
            int n0 = warpN * 32 + ni * 8 + lq;
            bf[ni][0] = Bs[buf][lr][n0];
            bf[ni][1] = Bs[buf][lr + 4][n0];
        }
        #pragma unroll
        for (int mi = 0; mi < 4; mi++)
            #pragma unroll
            for (int ni = 0; ni < 4; ni++)
                mma_bf16(acc[mi][ni], af[mi], bf[ni]);
    }

    #pragma unroll
    for (int mi = 0; mi < 4; mi++) {
        int r0 = mBase + warpM * 64 + mi * 16 + lq;
        #pragma unroll
        for (int ni = 0; ni < 4; ni++) {
            int c0 = nBase + warpN * 32 + ni * 8 + lr * 2;
            epi_store<MODE, NCOLS>(r0,     c0,     acc[mi][ni][0], bias, aux, out);
            epi_store<MODE, NCOLS>(r0,     c0 + 1, acc[mi][ni][1], bias, aux, out);
            epi_store<MODE, NCOLS>(r0 + 8, c0,     acc[mi][ni][2], bias, aux, out);
            epi_store<MODE, NCOLS>(r0 + 8, c0 + 1, acc[mi][ni][3], bias, aux, out);
        }
    }
}

// ---------------------------------------------------------------------------
// Attention: one block per (window, head). N=64, HD=32. (unchanged, fp32)
// ---------------------------------------------------------------------------
__global__ __launch_bounds__(128) void attn_kernel(
    const float* __restrict__ rpb, float* __restrict__ out)
{
    __shared__ float Qs[64][32];
    __shared__ float Ks[64][32];
    __shared__ float Vs[64][32];
    __shared__ float S[64][65];

    const int bh = blockIdx.x;
    const int wid = bh / 6, head = bh - wid * 6;
    const int w = wid & 63;
    const int t = threadIdx.x;

    const float* qb = g_qkv + (long)bh * 2048;
    const float* kb = qb + QKV_STRIDE;
    const float* vb = kb + QKV_STRIDE;

    #pragma unroll
    for (int i = t; i < 512; i += 128) {
        ((float4*)Qs)[i] = ((const float4*)qb)[i];
        ((float4*)Ks)[i] = ((const float4*)kb)[i];
        ((float4*)Vs)[i] = ((const float4*)vb)[i];
    }
    __syncthreads();

    const int row = t >> 1, half = t & 1;
    const int cb = half << 5;

    float q[32];
    #pragma unroll
    for (int i = 0; i < 8; i++) {
        float4 v = *(const float4*)&Qs[row][i * 4];
        q[i * 4] = v.x; q[i * 4 + 1] = v.y; q[i * 4 + 2] = v.z; q[i * 4 + 3] = v.w;
    }

    const int hb  = (w >> 3) << 3;
    const int wbx = (w & 7) << 3;
    const int rh = row >> 3, rw = row & 7;
    const int regRow = region(hb + rh) * 3 + region(wbx + rw);

    float mx = -1e30f;
    for (int c = 0; c < 32; c++) {
        int col = cb + c;
        float acc = 0.f;
        const float* kpt = &Ks[col][0];
        #pragma unroll
        for (int i = 0; i < 8; i++) {
            float4 kv = *(const float4*)(kpt + i * 4);
            acc += q[i * 4] * kv.x + q[i * 4 + 1] * kv.y +
                   q[i * 4 + 2] * kv.z + q[i * 4 + 3] * kv.w;
        }
        int ch = col >> 3, cw = col & 7;
        acc += rpb[((rh - ch + 7) * 15 + (rw - cw + 7)) * 6 + head];
        int regC = region(hb + ch) * 3 + region(wbx + cw);
        if (regC != regRow) acc -= 100.f;
        S[row][col] = acc;
        mx = fmaxf(mx, acc);
    }
    mx = fmaxf(mx, __shfl_xor_sync(0xffffffffu, mx, 1));

    float lsum = 0.f;
    for (int c = 0; c < 32; c++) {
        float e = __expf(S[row][cb + c] - mx);
        S[row][cb + c] = e;
        lsum += e;
    }
    lsum += __shfl_xor_sync(0xffffffffu, lsum, 1);
    float inv = 1.f / lsum;
    __syncthreads();

    float o[16] = {};
    const int hd0 = half << 4;
    for (int m = 0; m < 64; m++) {
        float p = S[row][m];
        const float* vp = &Vs[m][hd0];
        #pragma unroll
        for (int i = 0; i < 4; i++) {
            float4 vv = *(const float4*)(vp + i * 4);
            o[i * 4]     += p * vv.x;
            o[i * 4 + 1] += p * vv.y;
            o[i * 4 + 2] += p * vv.z;
            o[i * 4 + 3] += p * vv.w;
        }
    }
    float* op = out + ((long)(wid * 64 + row)) * 192 + head * 32 + hd0;
    #pragma unroll
    for (int i = 0; i < 16; i++) op[i] = o[i] * inv;
}

// ---------------------------------------------------------------------------
extern "C" void kernel_launch(void* const* d_in, const int* in_sizes, int n_in,
                              void* d_out, int out_size)
{
    const float* x      = (const float*)d_in[0];
    const float* rpb    = (const float*)d_in[1];
    const float* qkv_w  = (const float*)d_in[2];
    const float* qkv_b  = (const float*)d_in[3];
    const float* proj_w = (const float*)d_in[4];
    const float* proj_b = (const float*)d_in[5];
    const float* fc1_w  = (const float*)d_in[6];
    const float* fc1_b  = (const float*)d_in[7];
    const float* fc2_w  = (const float*)d_in[8];
    const float* fc2_b  = (const float*)d_in[9];
    float* out = (float*)d_out;

    float *qkv, *att, *x1, *h;
    cudaGetSymbolAddress((void**)&qkv, g_qkv);
    cudaGetSymbolAddress((void**)&att, g_att);
    cudaGetSymbolAddress((void**)&x1,  g_x1);
    cudaGetSymbolAddress((void**)&h,   g_h);

    dim3 blk(256);
    gemm_bf16<0, 192, 576><<<dim3(576 / 64, NROWS / 256), blk>>>(x, qkv_w, qkv_b, nullptr, qkv);
    attn_kernel<<<12288, 128>>>(rpb, att);
    gemm_bf16<1, 192, 192><<<dim3(192 / 64, NROWS / 256), blk>>>(att, proj_w, proj_b, x, x1);
    gemm_bf16<2, 192, 768><<<dim3(768 / 64, NROWS / 256), blk>>>(x1, fc1_w, fc1_b, nullptr, h);
    gemm_bf16<3, 768, 192><<<dim3(192 / 64, NROWS / 256), blk>>>(h, fc2_w, fc2_b, x1, out);
}

// round 5
// speedup vs baseline: 2.7892x; 1.2208x over previous
#include <cuda_runtime.h>
#include <cuda_bf16.h>
#include <math.h>

#define NROWS 131072
#define QKV_STRIDE 25165824ll

__device__ float g_qkv[3ll * 25165824];           // q,k,v fp32 (attention reads fp32)
__device__ __nv_bfloat16 g_xbf[25165824];         // x -> bf16
__device__ __nv_bfloat16 g_att[25165824];         // attention out (proj A input)
__device__ float g_x1[25165824];                  // residual-1 fp32
__device__ __nv_bfloat16 g_x1bf[25165824];        // residual-1 bf16 (fc1 A input)
__device__ __nv_bfloat16 g_h[100663296ll];        // gelu out bf16 (fc2 A input)
__device__ __nv_bfloat16 g_wbf[442368];           // qkv|proj|fc1|fc2 weights bf16

__device__ __forceinline__ int map_row(int r) {
    int wid = r >> 6, n = r & 63;
    int b = wid >> 6, w = wid & 63;
    int h  = ((w >> 3) << 3) + (n >> 3);
    int ww = ((w & 7) << 3) + (n & 7);
    int ho = (h + 4) & 63, wo = (ww + 4) & 63;
    return (b << 12) + (ho << 6) + wo;
}

__device__ __forceinline__ int region(int x) { return x < 56 ? 0 : (x < 60 ? 1 : 2); }

__device__ __forceinline__ void cpa16(unsigned s, const void* g) {
    asm volatile("cp.async.cg.shared.global [%0], [%1], 16;" :: "r"(s), "l"(g));
}
#define CP_COMMIT() asm volatile("cp.async.commit_group;")
#define CP_WAIT1()  asm volatile("cp.async.wait_group 1;")

__device__ __forceinline__ void ldsm4(unsigned* r, unsigned a) {
    asm volatile("ldmatrix.sync.aligned.m8n8.x4.shared.b16 {%0,%1,%2,%3}, [%4];"
        : "=r"(r[0]), "=r"(r[1]), "=r"(r[2]), "=r"(r[3]) : "r"(a));
}
__device__ __forceinline__ void ldsm4t(unsigned* r, unsigned a) {
    asm volatile("ldmatrix.sync.aligned.m8n8.x4.trans.shared.b16 {%0,%1,%2,%3}, [%4];"
        : "=r"(r[0]), "=r"(r[1]), "=r"(r[2]), "=r"(r[3]) : "r"(a));
}
__device__ __forceinline__ void mma_bf16(float* d, const unsigned* a, const unsigned* b) {
    asm volatile(
        "mma.sync.aligned.m16n8k16.row.col.f32.bf16.bf16.f32 "
        "{%0,%1,%2,%3}, {%4,%5,%6,%7}, {%8,%9}, {%0,%1,%2,%3};"
        : "+f"(d[0]), "+f"(d[1]), "+f"(d[2]), "+f"(d[3])
        : "r"(a[0]), "r"(a[1]), "r"(a[2]), "r"(a[3]), "r"(b[0]), "r"(b[1]));
}

template<int MODE, int NCOLS>
__device__ __forceinline__ void epi_store(
    int r, int c, float v, const float* __restrict__ bias,
    const float* __restrict__ aux, float* __restrict__ outf,
    __nv_bfloat16* __restrict__ outh)
{
    v += bias[c];
    if (MODE == 0) {
        int which = c / 192, rem = c % 192;
        int head = rem >> 5, hd = rem & 31;
        if (which == 0) v *= 0.17677669529663689f;
        int wid = r >> 6, n = r & 63;
        outf[(long)which * QKV_STRIDE + (((long)(wid * 6 + head) * 64 + n) * 32 + hd)] = v;
    } else if (MODE == 1) {
        long o = (long)map_row(r) * 192 + c;
        float s = aux[o] + v;
        outf[o] = s;
        outh[o] = __float2bfloat16(s);
    } else if (MODE == 2) {
        float g = 0.5f * v * (1.0f + erff(v * 0.7071067811865476f));
        outh[(long)r * NCOLS + c] = __float2bfloat16(g);
    } else {
        long o = (long)r * NCOLS + c;
        outf[o] = aux[o] + v;
    }
}

// ---------------------------------------------------------------------------
// bf16 GEMM: block 128x64, BK=32, 3-stage cp.async pipeline, ldmatrix frags.
// 8 warps (4M x 2N), warp tile 32x32 = 2x4 m16n8k16 frags.
// A smem rows 80B (40 bf16) pad; B smem rows 144B (72 bf16) pad — LDSM
// phases conflict-free for both.
// ---------------------------------------------------------------------------
template<int MODE, int K, int NCOLS>
__global__ __launch_bounds__(256, 3) void gemm_bf16(
    const __nv_bfloat16* __restrict__ A, const __nv_bfloat16* __restrict__ Bm,
    const float* __restrict__ bias, const float* __restrict__ aux,
    float* __restrict__ outf, __nv_bfloat16* __restrict__ outh)
{
    __shared__ __align__(16) __nv_bfloat16 Asm[3 * 128 * 40];
    __shared__ __align__(16) __nv_bfloat16 Bsm[3 * 32 * 72];

    const int mBase = blockIdx.y * 128;
    const int nBase = blockIdx.x * 64;
    const int t = threadIdx.x;
    const int lane = t & 31, warp = t >> 5;
    const int warpM = warp >> 1, warpN = warp & 1;
    const int lq = lane >> 2, lr = lane & 3;

    const unsigned aBase = (unsigned)__cvta_generic_to_shared(Asm);
    const unsigned bBase = (unsigned)__cvta_generic_to_shared(Bsm);

    // A loader: 2 rows per thread (ar, ar+64), 16B chunk (t&3)
    const int ar = t >> 2;
    const int ac = (t & 3) * 8;
    long row1 = (MODE == 0) ? (long)map_row(mBase + ar)      : (long)(mBase + ar);
    long row2 = (MODE == 0) ? (long)map_row(mBase + ar + 64) : (long)(mBase + ar + 64);
    const __nv_bfloat16* Ap1 = A + row1 * K + ac;
    const __nv_bfloat16* Ap2 = A + row2 * K + ac;
    const unsigned sA1 = aBase + ar * 80 + (t & 3) * 16;
    const unsigned sA2 = sA1 + 64 * 80;
    // B loader: row k = t>>3, 16B chunk (t&7)
    const int bk = t >> 3;
    const __nv_bfloat16* Bp = Bm + (long)bk * NCOLS + nBase + (t & 7) * 8;
    const unsigned sB = bBase + bk * 144 + (t & 7) * 16;

    float acc[2][4][4];
    #pragma unroll
    for (int mi = 0; mi < 2; mi++)
        #pragma unroll
        for (int ni = 0; ni < 4; ni++)
            #pragma unroll
            for (int e = 0; e < 4; e++) acc[mi][ni][e] = 0.f;

    const int NK = K / 32;
    // prologue: stages 0,1
    #pragma unroll
    for (int s = 0; s < 2; s++) {
        cpa16(sA1 + s * 10240, Ap1 + s * 32);
        cpa16(sA2 + s * 10240, Ap2 + s * 32);
        cpa16(sB + s * 4608, Bp + (long)s * 32 * NCOLS);
        CP_COMMIT();
    }

    for (int kt = 0; kt < NK; kt++) {
        const int s = kt % 3;
        CP_WAIT1();
        __syncthreads();
        if (kt + 2 < NK) {
            const int s2 = (kt + 2) % 3;
            cpa16(sA1 + s2 * 10240, Ap1 + (kt + 2) * 32);
            cpa16(sA2 + s2 * 10240, Ap2 + (kt + 2) * 32);
            cpa16(sB + s2 * 4608, Bp + (long)(kt + 2) * 32 * NCOLS);
        }
        CP_COMMIT();

        const unsigned as0 = aBase + s * 10240;
        const unsigned bs0 = bBase + s * 4608;
        #pragma unroll
        for (int k16 = 0; k16 < 2; k16++) {
            unsigned af[2][4], bq[2][4];
            #pragma unroll
            for (int mi = 0; mi < 2; mi++)
                ldsm4(af[mi], as0 + (warpM * 32 + mi * 16 + (lane & 15)) * 80
                              + k16 * 32 + (lane >> 4) * 16);
            #pragma unroll
            for (int g = 0; g < 2; g++)
                ldsm4t(bq[g], bs0 + (k16 * 16 + (lane & 15)) * 144
                              + (warpN * 32 + g * 16 + ((lane >> 4) << 3)) * 2);
            #pragma unroll
            for (int mi = 0; mi < 2; mi++)
                #pragma unroll
                for (int ni = 0; ni < 4; ni++)
                    mma_bf16(acc[mi][ni], af[mi], &bq[ni >> 1][(ni & 1) * 2]);
        }
    }

    #pragma unroll
    for (int mi = 0; mi < 2; mi++) {
        int r0 = mBase + warpM * 32 + mi * 16 + lq;
        #pragma unroll
        for (int ni = 0; ni < 4; ni++) {
            int c0 = nBase + warpN * 32 + ni * 8 + lr * 2;
            epi_store<MODE, NCOLS>(r0,     c0,     acc[mi][ni][0], bias, aux, outf, outh);
            epi_store<MODE, NCOLS>(r0,     c0 + 1, acc[mi][ni][1], bias, aux, outf, outh);
            epi_store<MODE, NCOLS>(r0 + 8, c0,     acc[mi][ni][2], bias, aux, outf, outh);
            epi_store<MODE, NCOLS>(r0 + 8, c0 + 1, acc[mi][ni][3], bias, aux, outf, outh);
        }
    }
}

// ---------------------------------------------------------------------------
__global__ void f2bf(const float* __restrict__ in, __nv_bfloat16* __restrict__ out, int n) {
    int i = (blockIdx.x * blockDim.x + threadIdx.x) * 4;
    if (i >= n) return;
    float4 v = *(const float4*)(in + i);
    *(__nv_bfloat162*)(out + i)     = __floats2bfloat162_rn(v.x, v.y);
    *(__nv_bfloat162*)(out + i + 2) = __floats2bfloat162_rn(v.z, v.w);
}

// ---------------------------------------------------------------------------
// Attention: one block per (window, head). Reads fp32 qkv, writes bf16 att.
// ---------------------------------------------------------------------------
__global__ __launch_bounds__(128) void attn_kernel(
    const float* __restrict__ rpb, __nv_bfloat16* __restrict__ out)
{
    __shared__ float Qs[64][32];
    __shared__ float Ks[64][32];
    __shared__ float Vs[64][32];
    __shared__ float S[64][65];

    const int bh = blockIdx.x;
    const int wid = bh / 6, head = bh - wid * 6;
    const int w = wid & 63;
    const int t = threadIdx.x;

    const float* qb = g_qkv + (long)bh * 2048;
    const float* kb = qb + QKV_STRIDE;
    const float* vb = kb + QKV_STRIDE;

    #pragma unroll
    for (int i = t; i < 512; i += 128) {
        ((float4*)Qs)[i] = ((const float4*)qb)[i];
        ((float4*)Ks)[i] = ((const float4*)kb)[i];
        ((float4*)Vs)[i] = ((const float4*)vb)[i];
    }
    __syncthreads();

    const int row = t >> 1, half = t & 1;
    const int cb = half << 5;

    float q[32];
    #pragma unroll
    for (int i = 0; i < 8; i++) {
        float4 v = *(const float4*)&Qs[row][i * 4];
        q[i * 4] = v.x; q[i * 4 + 1] = v.y; q[i * 4 + 2] = v.z; q[i * 4 + 3] = v.w;
    }

    const int hb  = (w >> 3) << 3;
    const int wbx = (w & 7) << 3;
    const int rh = row >> 3, rw = row & 7;
    const int regRow = region(hb + rh) * 3 + region(wbx + rw);

    float mx = -1e30f;
    for (int c = 0; c < 32; c++) {
        int col = cb + c;
        float acc = 0.f;
        const float* kpt = &Ks[col][0];
        #pragma unroll
        for (int i = 0; i < 8; i++) {
            float4 kv = *(const float4*)(kpt + i * 4);
            acc += q[i * 4] * kv.x + q[i * 4 + 1] * kv.y +
                   q[i * 4 + 2] * kv.z + q[i * 4 + 3] * kv.w;
        }
        int ch = col >> 3, cw = col & 7;
        acc += rpb[((rh - ch + 7) * 15 + (rw - cw + 7)) * 6 + head];
        int regC = region(hb + ch) * 3 + region(wbx + cw);
        if (regC != regRow) acc -= 100.f;
        S[row][col] = acc;
        mx = fmaxf(mx, acc);
    }
    mx = fmaxf(mx, __shfl_xor_sync(0xffffffffu, mx, 1));

    float lsum = 0.f;
    for (int c = 0; c < 32; c++) {
        float e = __expf(S[row][cb + c] - mx);
        S[row][cb + c] = e;
        lsum += e;
    }
    lsum += __shfl_xor_sync(0xffffffffu, lsum, 1);
    float inv = 1.f / lsum;
    __syncthreads();

    float o[16] = {};
    const int hd0 = half << 4;
    for (int m = 0; m < 64; m++) {
        float p = S[row][m];
        const float* vp = &Vs[m][hd0];
        #pragma unroll
        for (int i = 0; i < 4; i++) {
            float4 vv = *(const float4*)(vp + i * 4);
            o[i * 4]     += p * vv.x;
            o[i * 4 + 1] += p * vv.y;
            o[i * 4 + 2] += p * vv.z;
            o[i * 4 + 3] += p * vv.w;
        }
    }
    __nv_bfloat16* op = out + ((long)(wid * 64 + row)) * 192 + head * 32 + hd0;
    #pragma unroll
    for (int i = 0; i < 8; i++)
        ((__nv_bfloat162*)op)[i] = __floats2bfloat162_rn(o[2 * i] * inv, o[2 * i + 1] * inv);
}

// ---------------------------------------------------------------------------
extern "C" void kernel_launch(void* const* d_in, const int* in_sizes, int n_in,
                              void* d_out, int out_size)
{
    const float* x      = (const float*)d_in[0];
    const float* rpb    = (const float*)d_in[1];
    const float* qkv_w  = (const float*)d_in[2];
    const float* qkv_b  = (const float*)d_in[3];
    const float* proj_w = (const float*)d_in[4];
    const float* proj_b = (const float*)d_in[5];
    const float* fc1_w  = (const float*)d_in[6];
    const float* fc1_b  = (const float*)d_in[7];
    const float* fc2_w  = (const float*)d_in[8];
    const float* fc2_b  = (const float*)d_in[9];
    float* out = (float*)d_out;

    float *qkv, *x1;
    __nv_bfloat16 *xbf, *att, *x1bf, *h, *wbf;
    cudaGetSymbolAddress((void**)&qkv,  g_qkv);
    cudaGetSymbolAddress((void**)&xbf,  g_xbf);
    cudaGetSymbolAddress((void**)&att,  g_att);
    cudaGetSymbolAddress((void**)&x1,   g_x1);
    cudaGetSymbolAddress((void**)&x1bf, g_x1bf);
    cudaGetSymbolAddress((void**)&h,    g_h);
    cudaGetSymbolAddress((void**)&wbf,  g_wbf);

    f2bf<<<25165824 / 4 / 256, 256>>>(x, xbf, 25165824);
    f2bf<<<(110592 / 4 + 255) / 256, 256>>>(qkv_w,  wbf,          110592);
    f2bf<<<(36864  / 4 + 255) / 256, 256>>>(proj_w, wbf + 110592, 36864);
    f2bf<<<(147456 / 4 + 255) / 256, 256>>>(fc1_w,  wbf + 147456, 147456);
    f2bf<<<(147456 / 4 + 255) / 256, 256>>>(fc2_w,  wbf + 294912, 147456);

    dim3 blk(256);
    gemm_bf16<0, 192, 576><<<dim3(9, 1024), blk>>>(xbf, wbf, qkv_b, nullptr, qkv, nullptr);
    attn_kernel<<<12288, 128>>>(rpb, att);
    gemm_bf16<1, 192, 192><<<dim3(3, 1024), blk>>>(att, wbf + 110592, proj_b, x, x1, x1bf);
    gemm_bf16<2, 192, 768><<<dim3(12, 1024), blk>>>(x1bf, wbf + 147456, fc1_b, nullptr, nullptr, h);
    gemm_bf16<3, 768, 192><<<dim3(3, 1024), blk>>>(h, wbf + 294912, fc2_b, x1, out, nullptr);
}